// round 8
// baseline (speedup 1.0000x reference)
#include <cuda_runtime.h>
#include <cuda_fp16.h>
#include <math.h>
#include <stdint.h>

#define BB 8
#define SS 2048
#define DD 768

// Scratch (allocation-free __device__ globals). fp16 operands everywhere.
__device__ __half g_QK[BB * SS * (2 * DD)];  // Q|K interleaved: [B*S, 1536]
__device__ __half g_VT[BB * DD * SS];        // V transposed per batch: [B][D][S]
__device__ __half g_Xh[BB * SS * DD];        // x in fp16
__device__ __half g_Wh[3 * DD * DD];         // Wq|Wk|Wv in fp16
__device__ __half g_At[BB * SS * SS];        // softmax output in fp16

__device__ __forceinline__ uint32_t swz(uint32_t byte) {
    return byte ^ ((byte >> 3) & 0x70);
}
__device__ __forceinline__ void ldsm4(uint32_t& r0, uint32_t& r1,
                                      uint32_t& r2, uint32_t& r3, uint32_t addr) {
    asm volatile("ldmatrix.sync.aligned.m8n8.x4.shared.b16 {%0,%1,%2,%3}, [%4];"
                 : "=r"(r0), "=r"(r1), "=r"(r2), "=r"(r3) : "r"(addr));
}
__device__ __forceinline__ void mma16(float* c, const uint32_t* a,
                                      uint32_t b0, uint32_t b1) {
    asm volatile(
        "mma.sync.aligned.m16n8k16.row.col.f32.f16.f16.f32 "
        "{%0,%1,%2,%3}, {%4,%5,%6,%7}, {%8,%9}, {%0,%1,%2,%3};"
        : "+f"(c[0]), "+f"(c[1]), "+f"(c[2]), "+f"(c[3])
        : "r"(a[0]), "r"(a[1]), "r"(a[2]), "r"(a[3]), "r"(b0), "r"(b1));
}
__device__ __forceinline__ void cp16(uint32_t dst, const void* src) {
    asm volatile("cp.async.cg.shared.global [%0], [%1], 16;" :: "r"(dst), "l"(src));
}
__device__ __forceinline__ void cp_commit() {
    asm volatile("cp.async.commit_group;" ::: "memory");
}
__device__ __forceinline__ void cp_wait1() {
    asm volatile("cp.async.wait_group 1;" ::: "memory");
}

// ---------------------------------------------------------------------------
// Elementwise fp32 -> fp16.
// ---------------------------------------------------------------------------
__global__ __launch_bounds__(256) void cvt_f16_kernel(
    const float4* __restrict__ in, uint2* __restrict__ out, int n4)
{
    int i = blockIdx.x * 256 + threadIdx.x;
    if (i < n4) {
        float4 v = in[i];
        __half2 h01 = __floats2half2_rn(v.x, v.y);
        __half2 h23 = __floats2half2_rn(v.z, v.w);
        uint2 u;
        u.x = *reinterpret_cast<uint32_t*>(&h01);
        u.y = *reinterpret_cast<uint32_t*>(&h23);
        out[i] = u;
    }
}

// ---------------------------------------------------------------------------
// TN fp16 tensor-core GEMM:  C[m,n] = alpha * sum_k A[m,k]*B[n,k]
// A: MxK fp16 row-major pitch lda, B: NxK fp16 row-major pitch ldb.
// OUT=0: C fp32; OUT=1: C fp16 (pitch N). Batched via blockIdx.z.
// CTA tile 256x128, K-chunks of 64 (128B SW128 rows), 3-stage cp.async,
// 8 warps as 4m x 2n, warp tile 64x64 of m16n8k16 MMAs.
// Requires M%256==0, N%128==0, K%64==0.
// ---------------------------------------------------------------------------
#define CK 64
#define A_BYTES   32768                     // 256 rows * 128B
#define STG_BYTES 49152                     // A 32KB + B 16KB
#define DYN_SMEM  (3 * STG_BYTES)           // 147456

template <int OUT>
__global__ __launch_bounds__(256, 1) void gemm_tn_f16(
    const __half* __restrict__ A, const __half* __restrict__ B,
    void* __restrict__ Cv, int M, int N, int K, int lda, int ldb,
    long long sA, long long sB, long long sC, float alpha)
{
    extern __shared__ __align__(1024) uint8_t dynsm[];

    const int tid  = threadIdx.x;
    const int lane = tid & 31;
    const int warp = tid >> 5;
    const int wm   = warp & 3;     // 0..3 (m, 64 rows each)
    const int wn   = warp >> 2;    // 0..1 (n, 64 cols each)
    const int m0   = blockIdx.y * 256;
    const int n0   = blockIdx.x * 128;

    A += (long long)blockIdx.z * sA;
    B += (long long)blockIdx.z * sB;

    const uint32_t smbase = (uint32_t)__cvta_generic_to_shared(dynsm);

    // Fill coords: 128B rows (64 halves), 16B granules (8 halves) per thread.
    // A: 2048 granules/chunk (8/thr), B: 1024 (4/thr).
    const int r0  = tid >> 3;            // 0..31
    const int gg  = tid & 7;
    const uint32_t g16 = (uint32_t)gg * 16;

    const __half* pa0 = A + (long long)(m0 + r0) * lda + gg * 8;
    const __half* pb0 = B + (long long)(n0 + r0) * ldb + gg * 8;
    const long long stepa = 32LL * lda;
    const long long stepb = 32LL * ldb;
    uint32_t oa[8], ob[4];
    #pragma unroll
    for (int j = 0; j < 8; j++)
        oa[j] = swz((uint32_t)(r0 + 32 * j) * 128 + g16);
    #pragma unroll
    for (int j = 0; j < 4; j++)
        ob[j] = swz((uint32_t)(r0 + 32 * j) * 128 + g16) + A_BYTES;

    const int KT = K / CK;

    #define FILL(t) do {                                          \
        uint32_t sb = smbase + ((t) % 3) * STG_BYTES;             \
        int ko = (t) * CK;                                        \
        _Pragma("unroll")                                         \
        for (int j = 0; j < 8; j++)                               \
            cp16(sb + oa[j], pa0 + stepa * j + ko);               \
        _Pragma("unroll")                                         \
        for (int j = 0; j < 4; j++)                               \
            cp16(sb + ob[j], pb0 + stepb * j + ko);               \
    } while (0)

    FILL(0); cp_commit();
    FILL(1); cp_commit();

    float acc[4][8][4] = {};

    // Hoisted swizzled ldsm base offsets (validated R7 algebra).
    const int lrow = (lane & 7) + ((lane >> 3) & 1) * 8;
    const uint32_t glo = (uint32_t)(lane >> 4) * 16;
    uint32_t aoff[4], boff[4];
    #pragma unroll
    for (int mi = 0; mi < 4; mi++)
        aoff[mi] = swz((uint32_t)((wm * 64 + mi * 16 + lrow) * 128)) ^ glo;
    #pragma unroll
    for (int l = 0; l < 4; l++)
        boff[l] = (swz((uint32_t)((wn * 64 + l * 16 + lrow) * 128)) ^ glo) + A_BYTES;

    for (int i = 0; i < KT; i++) {
        cp_wait1();
        __syncthreads();
        if (i + 2 < KT) FILL(i + 2);
        cp_commit();

        const uint32_t stage = smbase + (i % 3) * STG_BYTES;

        #pragma unroll
        for (int ks = 0; ks < 4; ks++) {             // k16 steps in k64
            const uint32_t gx = (uint32_t)(ks * 32); // bits 5-6, disjoint from glo
            uint32_t a[4][4], b[4][4];
            #pragma unroll
            for (int mi = 0; mi < 4; mi++)
                ldsm4(a[mi][0], a[mi][1], a[mi][2], a[mi][3],
                      stage + (aoff[mi] ^ gx));
            #pragma unroll
            for (int l = 0; l < 4; l++)
                ldsm4(b[l][0], b[l][1], b[l][2], b[l][3],
                      stage + (boff[l] ^ gx));
            #pragma unroll
            for (int mi = 0; mi < 4; mi++)
                #pragma unroll
                for (int j = 0; j < 8; j++) {
                    const int l = j >> 1, o = j & 1;
                    mma16(acc[mi][j], a[mi], b[l][o], b[l][o + 2]);
                }
        }
        __syncthreads();
    }
    #undef FILL

    // Epilogue (m16n8 layout: rows r, r+8; adjacent col pairs).
    const int rr0 = m0 + wm * 64 + (lane >> 2);
    const int cc0 = n0 + wn * 64 + (lane & 3) * 2;
    if (OUT == 0) {
        float* C = (float*)Cv + (long long)blockIdx.z * sC;
        #pragma unroll
        for (int mi = 0; mi < 4; mi++)
            #pragma unroll
            for (int ni = 0; ni < 8; ni++) {
                float* p = C + (long long)(rr0 + mi * 16) * N + cc0 + ni * 8;
                float2 v0, v1;
                v0.x = acc[mi][ni][0] * alpha; v0.y = acc[mi][ni][1] * alpha;
                v1.x = acc[mi][ni][2] * alpha; v1.y = acc[mi][ni][3] * alpha;
                *(float2*)p = v0;
                *(float2*)(p + 8LL * N) = v1;
            }
    } else {
        __half* C = (__half*)Cv + (long long)blockIdx.z * sC;
        #pragma unroll
        for (int mi = 0; mi < 4; mi++)
            #pragma unroll
            for (int ni = 0; ni < 8; ni++) {
                __half* p = C + (long long)(rr0 + mi * 16) * N + cc0 + ni * 8;
                *(__half2*)p =
                    __floats2half2_rn(acc[mi][ni][0] * alpha, acc[mi][ni][1] * alpha);
                *(__half2*)(p + 8LL * N) =
                    __floats2half2_rn(acc[mi][ni][2] * alpha, acc[mi][ni][3] * alpha);
            }
    }
}

// ---------------------------------------------------------------------------
// Row softmax (len 2048), shuffle reductions. Exact fp32 -> attn (output),
// fp16 copy -> at16 (consumed by AV GEMM).
// ---------------------------------------------------------------------------
__global__ __launch_bounds__(256) void softmax_kernel(
    float* __restrict__ attn, __half* __restrict__ at16)
{
    __shared__ float sm_max[8], sm_sum[8];
    const long long row = blockIdx.x;
    float2*  p2 = (float2*)(attn + row * (long long)SS);
    __half2* q2 = (__half2*)(at16 + row * (long long)SS);
    const int tid  = threadIdx.x;
    const int lane = tid & 31;
    const int warp = tid >> 5;

    float2 v[4];
    float mx = -1e30f;
    #pragma unroll
    for (int i = 0; i < 4; i++) {
        v[i] = p2[tid + i * 256];
        mx = fmaxf(mx, fmaxf(v[i].x, v[i].y));
    }
    #pragma unroll
    for (int o = 16; o > 0; o >>= 1)
        mx = fmaxf(mx, __shfl_xor_sync(0xFFFFFFFFu, mx, o));
    if (lane == 0) sm_max[warp] = mx;
    __syncthreads();
    mx = sm_max[0];
    #pragma unroll
    for (int w = 1; w < 8; w++) mx = fmaxf(mx, sm_max[w]);

    float sum = 0.0f;
    #pragma unroll
    for (int i = 0; i < 4; i++) {
        v[i].x = __expf(v[i].x - mx);
        v[i].y = __expf(v[i].y - mx);
        sum += v[i].x + v[i].y;
    }
    #pragma unroll
    for (int o = 16; o > 0; o >>= 1)
        sum += __shfl_xor_sync(0xFFFFFFFFu, sum, o);
    if (lane == 0) sm_sum[warp] = sum;
    __syncthreads();
    sum = 0.0f;
    #pragma unroll
    for (int w = 0; w < 8; w++) sum += sm_sum[w];
    const float inv = 1.0f / sum;

    #pragma unroll
    for (int i = 0; i < 4; i++) {
        float r0 = v[i].x * inv, r1 = v[i].y * inv;
        p2[tid + i * 256] = make_float2(r0, r1);
        q2[tid + i * 256] = __floats2half2_rn(r0, r1);
    }
}

extern "C" void kernel_launch(void* const* d_in, const int* in_sizes, int n_in,
                              void* d_out, int out_size)
{
    const float* x  = (const float*)d_in[0];
    const float* Wq = (const float*)d_in[1];
    const float* Wk = (const float*)d_in[2];
    const float* Wv = (const float*)d_in[3];

    float* out  = (float*)d_out;                   // weighted_values [B,S,D]
    float* attn = out + (long long)BB * SS * DD;   // attention_weights [B,S,S]

    __half *QK, *VT, *Xh, *Wh, *At;
    cudaGetSymbolAddress((void**)&QK, g_QK);
    cudaGetSymbolAddress((void**)&VT, g_VT);
    cudaGetSymbolAddress((void**)&Xh, g_Xh);
    cudaGetSymbolAddress((void**)&Wh, g_Wh);
    cudaGetSymbolAddress((void**)&At, g_At);

    cudaFuncSetAttribute(gemm_tn_f16<0>,
                         cudaFuncAttributeMaxDynamicSharedMemorySize, DYN_SMEM);
    cudaFuncSetAttribute(gemm_tn_f16<1>,
                         cudaFuncAttributeMaxDynamicSharedMemorySize, DYN_SMEM);

    dim3 blk(256);
    const float alpha = 1.0f / sqrtf((float)DD);

    // fp32 -> fp16 operand conversion. Wq|Wk|Wv land contiguously in Wh.
    {
        int n4x = BB * SS * DD / 4;
        cvt_f16_kernel<<<(n4x + 255) / 256, blk>>>((const float4*)x, (uint2*)Xh, n4x);
        int n4w = DD * DD / 4;
        cvt_f16_kernel<<<(n4w + 255) / 256, blk>>>((const float4*)Wq, (uint2*)(Wh + 0LL * DD * DD), n4w);
        cvt_f16_kernel<<<(n4w + 255) / 256, blk>>>((const float4*)Wk, (uint2*)(Wh + 1LL * DD * DD), n4w);
        cvt_f16_kernel<<<(n4w + 255) / 256, blk>>>((const float4*)Wv, (uint2*)(Wh + 2LL * DD * DD), n4w);
    }

    // Fused Q|K projection: QK[m, 0:768]=Q, QK[m, 768:1536]=K (fp16 out).
    dim3 gqk((2 * DD) / 128, (BB * SS) / 256, 1);
    gemm_tn_f16<1><<<gqk, blk, DYN_SMEM>>>(Xh, Wh, QK,
        BB * SS, 2 * DD, DD, DD, DD, 0, 0, 0, 1.0f);

    // V^T: VT_b[d][s] = sum_k Wv[d][k] * x_b[s][k] (fp16 out). M=768%256==0.
    dim3 gv(SS / 128, DD / 256, BB);
    gemm_tn_f16<1><<<gv, blk, DYN_SMEM>>>(Wh + 2LL * DD * DD, Xh, VT,
        DD, SS, DD, DD, DD, 0, (long long)SS * DD, (long long)DD * SS, 1.0f);

    // Scores: attn_b = (Q_b @ K_b^T) * alpha (fp32 out).
    dim3 gs(SS / 128, SS / 256, BB);
    gemm_tn_f16<0><<<gs, blk, DYN_SMEM>>>(QK, QK + DD, attn,
        SS, SS, DD, 2 * DD, 2 * DD,
        (long long)SS * 2 * DD, (long long)SS * 2 * DD, (long long)SS * SS, alpha);

    // Softmax rows: exact fp32 -> attn, fp16 -> At.
    softmax_kernel<<<BB * SS, blk>>>(attn, At);

    // Weighted values: out_b[s][d] = sum_k At_b[s][k] * VT_b[d][k] (fp32 out).
    dim3 ga(DD / 128, SS / 256, BB);
    gemm_tn_f16<0><<<ga, blk, DYN_SMEM>>>(At, VT, out,
        SS, DD, SS, SS, SS,
        (long long)SS * SS, (long long)DD * SS, (long long)SS * DD, 1.0f);
}

// round 9
// speedup vs baseline: 1.0926x; 1.0926x over previous
#include <cuda_runtime.h>
#include <cuda_fp16.h>
#include <math.h>
#include <stdint.h>

#define BB 8
#define SS 2048
#define DD 768

// Scratch (allocation-free __device__ globals). fp16 operands everywhere.
__device__ __half g_QK[BB * SS * (2 * DD)];  // Q|K interleaved: [B*S, 1536]
__device__ __half g_VT[BB * DD * SS];        // V transposed per batch: [B][D][S]
__device__ __half g_Xh[BB * SS * DD];        // x in fp16
__device__ __half g_Wh[3 * DD * DD];         // Wq|Wk|Wv in fp16
__device__ __half g_At[BB * SS * SS];        // softmax output in fp16

__device__ __forceinline__ uint32_t swz(uint32_t byte) {
    return byte ^ ((byte >> 3) & 0x70);
}
__device__ __forceinline__ void ldsm4(uint32_t& r0, uint32_t& r1,
                                      uint32_t& r2, uint32_t& r3, uint32_t addr) {
    asm volatile("ldmatrix.sync.aligned.m8n8.x4.shared.b16 {%0,%1,%2,%3}, [%4];"
                 : "=r"(r0), "=r"(r1), "=r"(r2), "=r"(r3) : "r"(addr));
}
__device__ __forceinline__ void mma16(float* c, const uint32_t* a,
                                      uint32_t b0, uint32_t b1) {
    asm volatile(
        "mma.sync.aligned.m16n8k16.row.col.f32.f16.f16.f32 "
        "{%0,%1,%2,%3}, {%4,%5,%6,%7}, {%8,%9}, {%0,%1,%2,%3};"
        : "+f"(c[0]), "+f"(c[1]), "+f"(c[2]), "+f"(c[3])
        : "r"(a[0]), "r"(a[1]), "r"(a[2]), "r"(a[3]), "r"(b0), "r"(b1));
}
__device__ __forceinline__ void cp16(uint32_t dst, const void* src) {
    asm volatile("cp.async.cg.shared.global [%0], [%1], 16;" :: "r"(dst), "l"(src));
}
__device__ __forceinline__ void cp_commit() {
    asm volatile("cp.async.commit_group;" ::: "memory");
}
__device__ __forceinline__ void cp_wait1() {
    asm volatile("cp.async.wait_group 1;" ::: "memory");
}

// ---------------------------------------------------------------------------
// Fused elementwise fp32 -> fp16 over x, Wq, Wk, Wv (one launch).
// ---------------------------------------------------------------------------
__device__ __forceinline__ uint2 cvt4(float4 v) {
    __half2 h01 = __floats2half2_rn(v.x, v.y);
    __half2 h23 = __floats2half2_rn(v.z, v.w);
    uint2 u;
    u.x = *reinterpret_cast<uint32_t*>(&h01);
    u.y = *reinterpret_cast<uint32_t*>(&h23);
    return u;
}
__global__ __launch_bounds__(256) void cvt_all_kernel(
    const float4* __restrict__ x,
    const float4* __restrict__ wq, const float4* __restrict__ wk,
    const float4* __restrict__ wv,
    uint2* __restrict__ xh, uint2* __restrict__ wh, int n4x, int n4w)
{
    int i = blockIdx.x * 256 + threadIdx.x;
    if (i < n4x) {
        xh[i] = cvt4(x[i]);
    } else {
        int j = i - n4x;
        if (j < n4w)               wh[j] = cvt4(wq[j]);
        else if (j < 2 * n4w)      wh[j] = cvt4(wk[j - n4w]);
        else if (j < 3 * n4w)      wh[j] = cvt4(wv[j - 2 * n4w]);
    }
}

// ---------------------------------------------------------------------------
// GEMM body (R7-validated): TN fp16, C[m,n] = alpha * sum_k A[m,k]*B[n,k].
// Block tile 128x128, K-chunks of 64 (128B SW128 rows), 3-stage cp.async,
// 8 warps (4m x 2n), warp tile 32x64 of m16n8k16 MMAs.
// OUT=0: C fp32; OUT=1: C fp16 (both pitch N). Requires dims %128, K%64.
// ---------------------------------------------------------------------------
#define CK 64
#define STG_BYTES 32768            // A 16KB + B 16KB
#define DYN_SMEM  (3 * STG_BYTES)  // 98304; 2 CTAs/SM

template <int OUT>
__device__ __forceinline__ void gemm_body(
    const __half* __restrict__ A, const __half* __restrict__ B,
    void* __restrict__ Cv, int N, int K, int lda, int ldb,
    float alpha, int m0, int n0)
{
    extern __shared__ __align__(1024) uint8_t dynsm[];

    const int tid  = threadIdx.x;
    const int lane = tid & 31;
    const int warp = tid >> 5;
    const int wm   = warp >> 1;    // 0..3 (m, 32 rows each)
    const int wn   = warp & 1;     // 0..1 (n, 64 cols each)

    const uint32_t smbase = (uint32_t)__cvta_generic_to_shared(dynsm);

    // Fill coords: 128B rows (64 halves), 16B granules (8 halves).
    const int r0  = tid >> 3;            // 0..31
    const int gg  = tid & 7;
    const uint32_t g16 = (uint32_t)gg * 16;

    const __half* pa[4]; uint32_t oa[4];
    const __half* pb[4]; uint32_t ob[4];
    #pragma unroll
    for (int j = 0; j < 4; j++) {
        int row = r0 + 32 * j;
        pa[j] = A + (long long)(m0 + row) * lda + gg * 8;
        oa[j] = swz((uint32_t)row * 128 + g16);
        pb[j] = B + (long long)(n0 + row) * ldb + gg * 8;
        ob[j] = swz((uint32_t)row * 128 + g16) + 16384;
    }

    const int KT = K / CK;

    #define FILL(t) do {                                          \
        uint32_t sb = smbase + ((t) % 3) * STG_BYTES;             \
        int ko = (t) * CK;                                        \
        _Pragma("unroll")                                         \
        for (int j = 0; j < 4; j++) {                             \
            cp16(sb + oa[j], pa[j] + ko);                         \
            cp16(sb + ob[j], pb[j] + ko);                         \
        }                                                         \
    } while (0)

    FILL(0); cp_commit();
    FILL(1); cp_commit();

    float acc[2][8][4] = {};

    // Hoisted swizzled ldsm base offsets.
    const int lrow = (lane & 7) + ((lane >> 3) & 1) * 8;
    const uint32_t glo = (uint32_t)(lane >> 4) * 16;
    uint32_t aoff[2], boff[4];
    #pragma unroll
    for (int mi = 0; mi < 2; mi++)
        aoff[mi] = swz((uint32_t)((wm * 32 + mi * 16 + lrow) * 128)) ^ glo;
    #pragma unroll
    for (int l = 0; l < 4; l++)
        boff[l] = (swz((uint32_t)((wn * 64 + l * 16 + lrow) * 128)) ^ glo) + 16384;

    for (int i = 0; i < KT; i++) {
        cp_wait1();
        __syncthreads();
        if (i + 2 < KT) FILL(i + 2);
        cp_commit();

        const uint32_t stage = smbase + (i % 3) * STG_BYTES;

        #pragma unroll
        for (int ks = 0; ks < 4; ks++) {             // k16 steps in k64
            const uint32_t gx = (uint32_t)(ks * 32); // bits 5-6, disjoint from glo
            uint32_t a[2][4], b[4][4];
            #pragma unroll
            for (int mi = 0; mi < 2; mi++)
                ldsm4(a[mi][0], a[mi][1], a[mi][2], a[mi][3],
                      stage + (aoff[mi] ^ gx));
            #pragma unroll
            for (int l = 0; l < 4; l++)
                ldsm4(b[l][0], b[l][1], b[l][2], b[l][3],
                      stage + (boff[l] ^ gx));
            #pragma unroll
            for (int mi = 0; mi < 2; mi++)
                #pragma unroll
                for (int j = 0; j < 8; j++) {
                    const int l = j >> 1, o = j & 1;
                    mma16(acc[mi][j], a[mi], b[l][o], b[l][o + 2]);
                }
        }
        __syncthreads();
    }
    #undef FILL

    // Epilogue (m16n8 layout: rows r, r+8; adjacent col pairs).
    const int rr0 = m0 + wm * 32 + (lane >> 2);
    const int cc0 = n0 + wn * 64 + (lane & 3) * 2;
    if (OUT == 0) {
        float* C = (float*)Cv;
        #pragma unroll
        for (int mi = 0; mi < 2; mi++)
            #pragma unroll
            for (int ni = 0; ni < 8; ni++) {
                float* p = C + (long long)(rr0 + mi * 16) * N + cc0 + ni * 8;
                float2 v0, v1;
                v0.x = acc[mi][ni][0] * alpha; v0.y = acc[mi][ni][1] * alpha;
                v1.x = acc[mi][ni][2] * alpha; v1.y = acc[mi][ni][3] * alpha;
                *(float2*)p = v0;
                *(float2*)(p + 8LL * N) = v1;
            }
    } else {
        __half* C = (__half*)Cv;
        #pragma unroll
        for (int mi = 0; mi < 2; mi++)
            #pragma unroll
            for (int ni = 0; ni < 8; ni++) {
                __half* p = C + (long long)(rr0 + mi * 16) * N + cc0 + ni * 8;
                *(__half2*)p =
                    __floats2half2_rn(acc[mi][ni][0] * alpha, acc[mi][ni][1] * alpha);
                *(__half2*)(p + 8LL * N) =
                    __floats2half2_rn(acc[mi][ni][2] * alpha, acc[mi][ni][3] * alpha);
            }
    }
}

// ---------------------------------------------------------------------------
// Generic batched GEMM launcher kernel (scores / AV).
// ---------------------------------------------------------------------------
template <int OUT>
__global__ __launch_bounds__(256, 2) void gemm_tn_f16(
    const __half* __restrict__ A, const __half* __restrict__ B,
    void* __restrict__ Cv, int N, int K, int lda, int ldb,
    long long sA, long long sB, long long sC, float alpha)
{
    const __half* Ab = A + (long long)blockIdx.z * sA;
    const __half* Bb = B + (long long)blockIdx.z * sB;
    void* Cb = (OUT == 0)
        ? (void*)((float*)Cv + (long long)blockIdx.z * sC)
        : (void*)((__half*)Cv + (long long)blockIdx.z * sC);
    gemm_body<OUT>(Ab, Bb, Cb, N, K, lda, ldb, alpha,
                   blockIdx.y * 128, blockIdx.x * 128);
}

// ---------------------------------------------------------------------------
// Fused projection kernel: QK-proj tiles (bx < 1536) + VT tiles (bx >= 1536).
//   QK : QK[m, :] = x @ [Wq|Wk]^T  (M=16384, N=1536, K=768)
//   VT : VT_b[d][s] = sum_k Wv[d][k] * x_b[s][k]  (M=768, N=2048, batched)
// ---------------------------------------------------------------------------
#define QK_TILES 1536   // (2*DD/128) * (BB*SS/128) = 12 * 128
#define VT_TILES_PER_B 96  // (SS/128) * (DD/128) = 16 * 6

__global__ __launch_bounds__(256, 2) void proj_fused_kernel(
    const __half* __restrict__ Xh, const __half* __restrict__ Wh,
    __half* __restrict__ QK, __half* __restrict__ VT)
{
    const int bx = blockIdx.x;
    if (bx < QK_TILES) {
        const int nx = bx % 12;      // n-tile over 1536
        const int ny = bx / 12;      // m-tile over 16384
        gemm_body<1>(Xh, Wh, QK, 2 * DD, DD, DD, DD, 1.0f,
                     ny * 128, nx * 128);
    } else {
        const int i  = bx - QK_TILES;
        const int z  = i / VT_TILES_PER_B;   // batch
        const int r  = i % VT_TILES_PER_B;
        const int nx = r % 16;               // n-tile over SS
        const int ny = r / 16;               // m-tile over DD
        gemm_body<1>(Wh + 2LL * DD * DD,
                     Xh + (long long)z * SS * DD,
                     VT + (long long)z * DD * SS,
                     SS, DD, DD, DD, 1.0f, ny * 128, nx * 128);
    }
}

// ---------------------------------------------------------------------------
// Row softmax (len 2048), shuffle reductions. Exact fp32 -> attn (output),
// fp16 copy -> at16 (consumed by AV GEMM).
// ---------------------------------------------------------------------------
__global__ __launch_bounds__(256) void softmax_kernel(
    float* __restrict__ attn, __half* __restrict__ at16)
{
    __shared__ float sm_max[8], sm_sum[8];
    const long long row = blockIdx.x;
    float2*  p2 = (float2*)(attn + row * (long long)SS);
    __half2* q2 = (__half2*)(at16 + row * (long long)SS);
    const int tid  = threadIdx.x;
    const int lane = tid & 31;
    const int warp = tid >> 5;

    float2 v[4];
    float mx = -1e30f;
    #pragma unroll
    for (int i = 0; i < 4; i++) {
        v[i] = p2[tid + i * 256];
        mx = fmaxf(mx, fmaxf(v[i].x, v[i].y));
    }
    #pragma unroll
    for (int o = 16; o > 0; o >>= 1)
        mx = fmaxf(mx, __shfl_xor_sync(0xFFFFFFFFu, mx, o));
    if (lane == 0) sm_max[warp] = mx;
    __syncthreads();
    mx = sm_max[0];
    #pragma unroll
    for (int w = 1; w < 8; w++) mx = fmaxf(mx, sm_max[w]);

    float sum = 0.0f;
    #pragma unroll
    for (int i = 0; i < 4; i++) {
        v[i].x = __expf(v[i].x - mx);
        v[i].y = __expf(v[i].y - mx);
        sum += v[i].x + v[i].y;
    }
    #pragma unroll
    for (int o = 16; o > 0; o >>= 1)
        sum += __shfl_xor_sync(0xFFFFFFFFu, sum, o);
    if (lane == 0) sm_sum[warp] = sum;
    __syncthreads();
    sum = 0.0f;
    #pragma unroll
    for (int w = 0; w < 8; w++) sum += sm_sum[w];
    const float inv = 1.0f / sum;

    #pragma unroll
    for (int i = 0; i < 4; i++) {
        float r0 = v[i].x * inv, r1 = v[i].y * inv;
        p2[tid + i * 256] = make_float2(r0, r1);
        q2[tid + i * 256] = __floats2half2_rn(r0, r1);
    }
}

extern "C" void kernel_launch(void* const* d_in, const int* in_sizes, int n_in,
                              void* d_out, int out_size)
{
    const float* x  = (const float*)d_in[0];
    const float* Wq = (const float*)d_in[1];
    const float* Wk = (const float*)d_in[2];
    const float* Wv = (const float*)d_in[3];

    float* out  = (float*)d_out;                   // weighted_values [B,S,D]
    float* attn = out + (long long)BB * SS * DD;   // attention_weights [B,S,S]

    __half *QK, *VT, *Xh, *Wh, *At;
    cudaGetSymbolAddress((void**)&QK, g_QK);
    cudaGetSymbolAddress((void**)&VT, g_VT);
    cudaGetSymbolAddress((void**)&Xh, g_Xh);
    cudaGetSymbolAddress((void**)&Wh, g_Wh);
    cudaGetSymbolAddress((void**)&At, g_At);

    cudaFuncSetAttribute(gemm_tn_f16<0>,
                         cudaFuncAttributeMaxDynamicSharedMemorySize, DYN_SMEM);
    cudaFuncSetAttribute(proj_fused_kernel,
                         cudaFuncAttributeMaxDynamicSharedMemorySize, DYN_SMEM);

    dim3 blk(256);
    const float alpha = 1.0f / sqrtf((float)DD);

    // fp32 -> fp16: x + Wq + Wk + Wv in one launch.
    {
        int n4x = BB * SS * DD / 4;
        int n4w = DD * DD / 4;
        int tot = n4x + 3 * n4w;
        cvt_all_kernel<<<(tot + 255) / 256, blk>>>(
            (const float4*)x, (const float4*)Wq, (const float4*)Wk,
            (const float4*)Wv, (uint2*)Xh, (uint2*)Wh, n4x, n4w);
    }

    // Fused QK projection + V^T projection (one launch, 2304 CTAs).
    proj_fused_kernel<<<QK_TILES + BB * VT_TILES_PER_B, blk, DYN_SMEM>>>(
        Xh, Wh, QK, VT);

    // Scores: attn_b = (Q_b @ K_b^T) * alpha (fp32 out).
    dim3 gs(SS / 128, SS / 128, BB);
    gemm_tn_f16<0><<<gs, blk, DYN_SMEM>>>(QK, QK + DD, attn,
        SS, DD, 2 * DD, 2 * DD,
        (long long)SS * 2 * DD, (long long)SS * 2 * DD, (long long)SS * SS, alpha);

    // Softmax rows: exact fp32 -> attn, fp16 -> At.
    softmax_kernel<<<BB * SS, blk>>>(attn, At);

    // Weighted values: out_b[s][d] = sum_k At_b[s][k] * VT_b[d][k] (fp32 out).
    dim3 ga(DD / 128, SS / 128, BB);
    gemm_tn_f16<0><<<ga, blk, DYN_SMEM>>>(At, VT, out,
        DD, SS, SS, SS,
        (long long)SS * SS, (long long)DD * SS, (long long)SS * DD, 1.0f);
}